// round 3
// baseline (speedup 1.0000x reference)
#include <cuda_runtime.h>
#include <cstdint>
#include <cfloat>

#define NU 100000
#define NI 50000
#define DIM 128
#define EU 400000
#define EI 200000
#define BATCH 4096

// ---------------- scratch (static device memory) ------------------------------
__device__ float g_h[NU * DIM];
__device__ float g_out1[NU * DIM];
__device__ float g_uout2[NU * DIM];
__device__ float g_iout2[NI * DIM];
__device__ float g_ssrc[NU];
__device__ float g_sdst[NU];
__device__ float g_denom[NU];
__device__ float g_elog[EU];
__device__ float g_wt_hi[4][DIM * DIM];   // W^T (n-major, k contiguous), tf32-rounded hi
__device__ float g_wt_lo[4][DIM * DIM];   // tf32-rounded residual

// ---------------- helpers ------------------------------------------------------
__device__ __forceinline__ float elu_f(float x) { return x > 0.f ? x : expm1f(x); }

__device__ __forceinline__ float tf32_rna(float a) {
    uint32_t b; asm("cvt.rna.tf32.f32 %0, %1;" : "=r"(b) : "f"(a));
    return __uint_as_float(b);
}
__device__ __forceinline__ void red_add_v4(float* addr, float4 v) {
    asm volatile("red.global.add.v4.f32 [%0], {%1, %2, %3, %4};"
                 :: "l"(addr), "f"(v.x), "f"(v.y), "f"(v.z), "f"(v.w) : "memory");
}
__device__ __forceinline__ void mma_tf32(float* d, const uint32_t* a, const uint32_t* b) {
    asm volatile(
        "mma.sync.aligned.m16n8k8.row.col.f32.tf32.tf32.f32 "
        "{%0,%1,%2,%3}, {%4,%5,%6,%7}, {%8,%9}, {%0,%1,%2,%3};"
        : "+f"(d[0]), "+f"(d[1]), "+f"(d[2]), "+f"(d[3])
        : "r"(a[0]), "r"(a[1]), "r"(a[2]), "r"(a[3]), "r"(b[0]), "r"(b[1]));
}

// ---------------- W^T hi/lo prep ----------------------------------------------
__global__ void prep_w_kernel(const float* __restrict__ w0, const float* __restrict__ w1,
                              const float* __restrict__ w2, const float* __restrict__ w3) {
    int i = blockIdx.x * blockDim.x + threadIdx.x;        // 4*128*128 threads
    const float* W = (i < 16384) ? w0 : (i < 32768) ? w1 : (i < 49152) ? w2 : w3;
    int l = i >> 14;
    int j = i & 16383;
    int n = j >> 7, k = j & 127;
    float w = W[k * DIM + n];
    float hi = tf32_rna(w);
    g_wt_hi[l][n * DIM + k] = hi;
    g_wt_lo[l][n * DIM + k] = tf32_rna(w - hi);
}

// ---------------- init: zero out-accumulator + denom ---------------------------
__global__ void init_kernel(float* __restrict__ out, float* __restrict__ den, int N) {
    int i = blockIdx.x * blockDim.x + threadIdx.x;
    if (i < N * DIM) out[i] = 0.f;
    if (i < N) den[i] = 0.f;
}

// ---------------- TF32 HMMA GEMM + attention scalars ---------------------------
// h = act(x) @ W via 3-term tf32; also ssrc[r]=h[r]·a_src, sdst[r]=h[r]·a_dst.
// CTA: 128 rows x 128 cols, 256 threads (8 warps, each 64x32).
// SMEM layout (bytes):
#define SB_BH   0                         // Wt_hi [128n][132k]  (67584)
#define SB_BL   67584                     // Wt_lo
#define SB_AH   135168                    // A_hi chunk [128r][36k] (18432)
#define SB_AL   153600                    // A_lo chunk
#define SB_RED  172032                    // reduction buf: src[128][4], dst[128][4]
#define SMEM_TOT 176128

template <int ACT>
__global__ void __launch_bounds__(256, 1) gemm_mma_kernel(
    const float* __restrict__ x, const float* __restrict__ wt_hi, const float* __restrict__ wt_lo,
    const float* __restrict__ a_src, const float* __restrict__ a_dst,
    float* __restrict__ h, float* __restrict__ ssrc, float* __restrict__ sdst, int N)
{
    extern __shared__ char smem[];
    float* Bh = (float*)(smem + SB_BH);
    float* Bl = (float*)(smem + SB_BL);
    float* Ah = (float*)(smem + SB_AH);
    float* Al = (float*)(smem + SB_AL);
    float* red_s = (float*)(smem + SB_RED);
    float* red_d = red_s + 128 * 4;

    const int tid = threadIdx.x;
    const int lane = tid & 31;
    const int wid = tid >> 5;
    const int wm = wid & 1;                // row half  (64 rows)
    const int wn = wid >> 1;               // col group (32 cols)
    const int r0 = blockIdx.x * 128;

    // stage B = W^T hi/lo, [n][k] stride 132
    for (int i = tid; i < 128 * 32; i += 256) {
        int n = i >> 5, kq = i & 31;
        *(float4*)&Bh[n * 132 + kq * 4] = *(const float4*)(wt_hi + n * DIM + kq * 4);
        *(float4*)&Bl[n * 132 + kq * 4] = *(const float4*)(wt_lo + n * DIM + kq * 4);
    }

    float acc[4][4][4];
#pragma unroll
    for (int mt = 0; mt < 4; ++mt)
#pragma unroll
        for (int nt = 0; nt < 4; ++nt)
#pragma unroll
            for (int q = 0; q < 4; ++q) acc[mt][nt][q] = 0.f;

    // register prefetch of A chunk 0 (each thread owns 4 float4s of the 128x32 chunk)
    const int prow = tid >> 1;             // 2 threads per row, 4 float4 each
    const int pkq0 = (tid & 1) * 4;
    float4 pref[4];
#pragma unroll
    for (int q = 0; q < 4; ++q) {
        pref[q] = make_float4(0.f, 0.f, 0.f, 0.f);
        if (r0 + prow < N)
            pref[q] = *(const float4*)(x + (size_t)(r0 + prow) * DIM + (pkq0 + q) * 4);
    }

    for (int kc = 0; kc < 4; ++kc) {
        __syncthreads();   // smem A free (previous chunk consumed)
        // store prefetched chunk with ELU + tf32 split
#pragma unroll
        for (int q = 0; q < 4; ++q) {
            float4 v = pref[q];
            if (ACT) { v.x = elu_f(v.x); v.y = elu_f(v.y); v.z = elu_f(v.z); v.w = elu_f(v.w); }
            float4 hi = make_float4(tf32_rna(v.x), tf32_rna(v.y), tf32_rna(v.z), tf32_rna(v.w));
            float4 lo = make_float4(tf32_rna(v.x - hi.x), tf32_rna(v.y - hi.y),
                                    tf32_rna(v.z - hi.z), tf32_rna(v.w - hi.w));
            *(float4*)&Ah[prow * 36 + (pkq0 + q) * 4] = hi;
            *(float4*)&Al[prow * 36 + (pkq0 + q) * 4] = lo;
        }
        // prefetch next chunk
        if (kc < 3) {
#pragma unroll
            for (int q = 0; q < 4; ++q) {
                pref[q] = make_float4(0.f, 0.f, 0.f, 0.f);
                if (r0 + prow < N)
                    pref[q] = *(const float4*)(x + (size_t)(r0 + prow) * DIM
                                               + (kc + 1) * 32 + (pkq0 + q) * 4);
            }
        }
        __syncthreads();

        const uint32_t* uAh = (const uint32_t*)Ah;
        const uint32_t* uAl = (const uint32_t*)Al;
        const uint32_t* uBh = (const uint32_t*)Bh;
        const uint32_t* uBl = (const uint32_t*)Bl;

#pragma unroll
        for (int ks = 0; ks < 4; ++ks) {
            const int k0 = ks * 8;
            uint32_t bh[4][2], bl[4][2];
#pragma unroll
            for (int nt = 0; nt < 4; ++nt) {
                int bn = wn * 32 + nt * 8 + (lane >> 2);
                int bk = kc * 32 + k0 + (lane & 3);
                bh[nt][0] = uBh[bn * 132 + bk];
                bh[nt][1] = uBh[bn * 132 + bk + 4];
                bl[nt][0] = uBl[bn * 132 + bk];
                bl[nt][1] = uBl[bn * 132 + bk + 4];
            }
            uint32_t ah[4][4], al[4][4];
#pragma unroll
            for (int mt = 0; mt < 4; ++mt) {
                int ar = wm * 64 + mt * 16 + (lane >> 2);
                int ac = k0 + (lane & 3);
                ah[mt][0] = uAh[ar * 36 + ac];
                ah[mt][1] = uAh[(ar + 8) * 36 + ac];
                ah[mt][2] = uAh[ar * 36 + ac + 4];
                ah[mt][3] = uAh[(ar + 8) * 36 + ac + 4];
                al[mt][0] = uAl[ar * 36 + ac];
                al[mt][1] = uAl[(ar + 8) * 36 + ac];
                al[mt][2] = uAl[ar * 36 + ac + 4];
                al[mt][3] = uAl[(ar + 8) * 36 + ac + 4];
            }
#pragma unroll
            for (int mt = 0; mt < 4; ++mt)
#pragma unroll
                for (int nt = 0; nt < 4; ++nt) {
                    mma_tf32(acc[mt][nt], ah[mt], bh[nt]);
                    mma_tf32(acc[mt][nt], ah[mt], bl[nt]);
                    mma_tf32(acc[mt][nt], al[mt], bh[nt]);
                }
        }
    }

    // ---------------- epilogue: store h + attention scalar dots ----------------
    float asv[4][2], adv[4][2];
#pragma unroll
    for (int nt = 0; nt < 4; ++nt) {
        int c0 = wn * 32 + nt * 8 + 2 * (lane & 3);
        asv[nt][0] = a_src[c0];     asv[nt][1] = a_src[c0 + 1];
        adv[nt][0] = a_dst[c0];     adv[nt][1] = a_dst[c0 + 1];
    }

    float ps[8], pd[8];
#pragma unroll
    for (int q = 0; q < 8; ++q) { ps[q] = 0.f; pd[q] = 0.f; }

#pragma unroll
    for (int mt = 0; mt < 4; ++mt) {
        int ar = r0 + wm * 64 + mt * 16 + (lane >> 2);
#pragma unroll
        for (int nt = 0; nt < 4; ++nt) {
            int c0 = wn * 32 + nt * 8 + 2 * (lane & 3);
            if (ar < N)
                *(float2*)(h + (size_t)ar * DIM + c0) = make_float2(acc[mt][nt][0], acc[mt][nt][1]);
            if (ar + 8 < N)
                *(float2*)(h + (size_t)(ar + 8) * DIM + c0) = make_float2(acc[mt][nt][2], acc[mt][nt][3]);
            ps[mt * 2 + 0] += acc[mt][nt][0] * asv[nt][0] + acc[mt][nt][1] * asv[nt][1];
            ps[mt * 2 + 1] += acc[mt][nt][2] * asv[nt][0] + acc[mt][nt][3] * asv[nt][1];
            pd[mt * 2 + 0] += acc[mt][nt][0] * adv[nt][0] + acc[mt][nt][1] * adv[nt][1];
            pd[mt * 2 + 1] += acc[mt][nt][2] * adv[nt][0] + acc[mt][nt][3] * adv[nt][1];
        }
    }
    // reduce across the 4 lanes of each quad (they share the same rows)
#pragma unroll
    for (int q = 0; q < 8; ++q) {
        ps[q] += __shfl_xor_sync(0xFFFFFFFF, ps[q], 1);
        ps[q] += __shfl_xor_sync(0xFFFFFFFF, ps[q], 2);
        pd[q] += __shfl_xor_sync(0xFFFFFFFF, pd[q], 1);
        pd[q] += __shfl_xor_sync(0xFFFFFFFF, pd[q], 2);
    }
    __syncthreads();   // RED buffer shares smem lifetime; all mma reads done
    if ((lane & 3) == 0) {
#pragma unroll
        for (int mt = 0; mt < 4; ++mt) {
            int rl0 = wm * 64 + mt * 16 + (lane >> 2);
            red_s[rl0 * 4 + wn] = ps[mt * 2 + 0];
            red_s[(rl0 + 8) * 4 + wn] = ps[mt * 2 + 1];
            red_d[rl0 * 4 + wn] = pd[mt * 2 + 0];
            red_d[(rl0 + 8) * 4 + wn] = pd[mt * 2 + 1];
        }
    }
    __syncthreads();
    if (tid < 128) {
        int row = r0 + tid;
        if (row < N) {
            float s = red_s[tid * 4] + red_s[tid * 4 + 1] + red_s[tid * 4 + 2] + red_s[tid * 4 + 3];
            float d = red_d[tid * 4] + red_d[tid * 4 + 1] + red_d[tid * 4 + 2] + red_d[tid * 4 + 3];
            ssrc[row] = s;
            sdst[row] = d;
        }
    }
}

// ---------------- fused edge pass: logits + exp + segment sum -------------------
// max-shift dropped: coef = e_i / sum e_j is shift-invariant; logits bounded.
__global__ void edge_exp_kernel(const int* __restrict__ src, const int* __restrict__ dst,
                                const float* __restrict__ ssrc, const float* __restrict__ sdst,
                                const float* __restrict__ ev,
                                float* __restrict__ elog, float* __restrict__ den, int E)
{
    int e = blockIdx.x * blockDim.x + threadIdx.x;
    if (e < E) {
        int d = dst[e];
        float l = ssrc[src[e]] + sdst[d];
        l = l > 0.f ? l : 0.2f * l;
        float v = __expf(l) * ev[e];
        elog[e] = v;
        atomicAdd(den + d, v);
    }
}

// ---------------- scatter-add h[src]*coef into out[dst] ------------------------
__global__ void edge_aggregate_kernel(const int* __restrict__ src, const int* __restrict__ dst,
                                      const float* __restrict__ eval, const float* __restrict__ den,
                                      const float* __restrict__ h, float* __restrict__ out, int E)
{
    int lane = threadIdx.x & 31;
    int warp = (blockIdx.x * blockDim.x + threadIdx.x) >> 5;
    int nwarp = (gridDim.x * blockDim.x) >> 5;
    for (int e = warp; e < E; e += nwarp) {
        int s = src[e], d = dst[e];
        float coef = eval[e] / (den[d] + 1e-16f);
        float4 v = *(const float4*)(h + (size_t)s * DIM + lane * 4);
        v.x *= coef; v.y *= coef; v.z *= coef; v.w *= coef;
        red_add_v4(out + (size_t)d * DIM + lane * 4, v);
    }
}

// ---------------- final gather (deferred elu applied here) ----------------------
__global__ void gather_kernel(const float* __restrict__ uo, const float* __restrict__ io,
                              const int* __restrict__ uid, const int* __restrict__ iid,
                              float* __restrict__ out)
{
    int t = blockIdx.x * blockDim.x + threadIdx.x;
    int b = t >> 7, c = t & 127;
    if (b < BATCH)          out[t] = elu_f(uo[(size_t)uid[b] * DIM + c]);
    else if (b < 2 * BATCH) out[t] = elu_f(io[(size_t)iid[b - BATCH] * DIM + c]);
}

// ---------------- host orchestration -------------------------------------------
static void run_layer(const float* x, int act, const int* ei, const float* ev, int E, int N,
                      const float* wt_hi, const float* wt_lo,
                      const float* as, const float* ad,
                      float* h, float* outp, float* ssrc, float* sdst,
                      float* den, float* elog)
{
    const int TB = 256;
    init_kernel<<<(N * DIM + TB - 1) / TB, TB>>>(outp, den, N);
    if (act)
        gemm_mma_kernel<1><<<(N + 127) / 128, 256, SMEM_TOT>>>(x, wt_hi, wt_lo, as, ad, h, ssrc, sdst, N);
    else
        gemm_mma_kernel<0><<<(N + 127) / 128, 256, SMEM_TOT>>>(x, wt_hi, wt_lo, as, ad, h, ssrc, sdst, N);
    const int* src = ei;
    const int* dst = ei + E;
    edge_exp_kernel<<<(E + TB - 1) / TB, TB>>>(src, dst, ssrc, sdst, ev, elog, den, E);
    edge_aggregate_kernel<<<2048, 256>>>(src, dst, elog, den, h, outp, E);
}

extern "C" void kernel_launch(void* const* d_in, const int* in_sizes, int n_in,
                              void* d_out, int out_size)
{
    const int*   uedg = (const int*)d_in[0];
    const int*   iedg = (const int*)d_in[1];
    const int*   user_id = (const int*)d_in[2];
    const int*   item_id = (const int*)d_in[3];
    const float* uval = (const float*)d_in[4];
    const float* ival = (const float*)d_in[5];
    const float* umat = (const float*)d_in[6];
    const float* imat = (const float*)d_in[7];
    const float* W_u1 = (const float*)d_in[8];
    const float* as_u1 = (const float*)d_in[9];
    const float* ad_u1 = (const float*)d_in[10];
    const float* W_u2 = (const float*)d_in[11];
    const float* as_u2 = (const float*)d_in[12];
    const float* ad_u2 = (const float*)d_in[13];
    const float* W_i1 = (const float*)d_in[14];
    const float* as_i1 = (const float*)d_in[15];
    const float* ad_i1 = (const float*)d_in[16];
    const float* W_i2 = (const float*)d_in[17];
    const float* as_i2 = (const float*)d_in[18];
    const float* ad_i2 = (const float*)d_in[19];

    float *h, *out1, *uout2, *iout2, *ssrc, *sdst, *den, *elog, *wthi, *wtlo;
    cudaGetSymbolAddress((void**)&h, g_h);
    cudaGetSymbolAddress((void**)&out1, g_out1);
    cudaGetSymbolAddress((void**)&uout2, g_uout2);
    cudaGetSymbolAddress((void**)&iout2, g_iout2);
    cudaGetSymbolAddress((void**)&ssrc, g_ssrc);
    cudaGetSymbolAddress((void**)&sdst, g_sdst);
    cudaGetSymbolAddress((void**)&den, g_denom);
    cudaGetSymbolAddress((void**)&elog, g_elog);
    cudaGetSymbolAddress((void**)&wthi, g_wt_hi);
    cudaGetSymbolAddress((void**)&wtlo, g_wt_lo);

    cudaFuncSetAttribute(gemm_mma_kernel<0>, cudaFuncAttributeMaxDynamicSharedMemorySize, SMEM_TOT);
    cudaFuncSetAttribute(gemm_mma_kernel<1>, cudaFuncAttributeMaxDynamicSharedMemorySize, SMEM_TOT);

    // layer order: 0=i1, 1=i2, 2=u1, 3=u2
    prep_w_kernel<<<4 * DIM * DIM / 256, 256>>>(W_i1, W_i2, W_u1, W_u2);

    run_layer(imat, 0, iedg, ival, EI, NI, wthi + 0 * DIM * DIM, wtlo + 0 * DIM * DIM,
              as_i1, ad_i1, h, out1, ssrc, sdst, den, elog);
    run_layer(out1, 1, iedg, ival, EI, NI, wthi + 1 * DIM * DIM, wtlo + 1 * DIM * DIM,
              as_i2, ad_i2, h, iout2, ssrc, sdst, den, elog);
    run_layer(umat, 0, uedg, uval, EU, NU, wthi + 2 * DIM * DIM, wtlo + 2 * DIM * DIM,
              as_u1, ad_u1, h, out1, ssrc, sdst, den, elog);
    run_layer(out1, 1, uedg, uval, EU, NU, wthi + 3 * DIM * DIM, wtlo + 3 * DIM * DIM,
              as_u2, ad_u2, h, uout2, ssrc, sdst, den, elog);

    gather_kernel<<<(2 * BATCH * DIM) / 256, 256>>>(uout2, iout2, user_id, item_id, (float*)d_out);
}

// round 4
// speedup vs baseline: 1.1116x; 1.1116x over previous
#include <cuda_runtime.h>
#include <cstdint>
#include <cfloat>

#define NU 100000
#define NI 50000
#define DIM 128
#define EU 400000
#define EI 200000
#define BATCH 4096

// ---------------- scratch (static device memory) ------------------------------
__device__ float g_h[NU * DIM];
__device__ float g_out1[NU * DIM];
__device__ float g_uout2[NU * DIM];
__device__ float g_iout2[NI * DIM];
__device__ float g_ssrc[NU];
__device__ float g_sdst[NU];
__device__ float g_wt_hi[4][DIM * DIM];
__device__ float g_wt_lo[4][DIM * DIM];
// CSR scratch (rebuilt per graph)
__device__ int   g_cnt[NU + 1];
__device__ int   g_off[NU + 1];
__device__ int   g_btot[128];
__device__ int   g_work[NU];
__device__ int   g_csrc[EU];
__device__ float g_cev[EU];

// ---------------- helpers ------------------------------------------------------
__device__ __forceinline__ float elu_f(float x) { return x > 0.f ? x : expm1f(x); }

__device__ __forceinline__ float tf32_rna(float a) {
    uint32_t b; asm("cvt.rna.tf32.f32 %0, %1;" : "=r"(b) : "f"(a));
    return __uint_as_float(b);
}
__device__ __forceinline__ void mma_tf32(float* d, const uint32_t* a, const uint32_t* b) {
    asm volatile(
        "mma.sync.aligned.m16n8k8.row.col.f32.tf32.tf32.f32 "
        "{%0,%1,%2,%3}, {%4,%5,%6,%7}, {%8,%9}, {%0,%1,%2,%3};"
        : "+f"(d[0]), "+f"(d[1]), "+f"(d[2]), "+f"(d[3])
        : "r"(a[0]), "r"(a[1]), "r"(a[2]), "r"(a[3]), "r"(b[0]), "r"(b[1]));
}

// ---------------- W^T hi/lo prep ----------------------------------------------
__global__ void prep_w_kernel(const float* __restrict__ w0, const float* __restrict__ w1,
                              const float* __restrict__ w2, const float* __restrict__ w3) {
    int i = blockIdx.x * blockDim.x + threadIdx.x;
    const float* W = (i < 16384) ? w0 : (i < 32768) ? w1 : (i < 49152) ? w2 : w3;
    int l = i >> 14;
    int j = i & 16383;
    int n = j >> 7, k = j & 127;
    float w = W[k * DIM + n];
    float hi = tf32_rna(w);
    g_wt_hi[l][n * DIM + k] = hi;
    g_wt_lo[l][n * DIM + k] = tf32_rna(w - hi);
}

// ---------------- CSR build -----------------------------------------------------
__global__ void zero_cnt_kernel(int* __restrict__ cnt, int N) {
    int i = blockIdx.x * blockDim.x + threadIdx.x;
    if (i <= N) cnt[i] = 0;
}
__global__ void count_kernel(const int* __restrict__ dst, int* __restrict__ cnt, int E) {
    int e = blockIdx.x * blockDim.x + threadIdx.x;
    if (e < E) atomicAdd(&cnt[dst[e]], 1);
}
__global__ void __launch_bounds__(1024) scan_a_kernel(const int* __restrict__ cnt,
                                                      int* __restrict__ offs,
                                                      int* __restrict__ btot, int N) {
    __shared__ int sm[1024];
    int t = threadIdx.x;
    int i = blockIdx.x * 1024 + t;
    int v = (i < N) ? cnt[i] : 0;
    sm[t] = v;
    __syncthreads();
#pragma unroll
    for (int s = 1; s < 1024; s <<= 1) {
        int u = (t >= s) ? sm[t - s] : 0;
        __syncthreads();
        sm[t] += u;
        __syncthreads();
    }
    if (i < N) offs[i] = sm[t] - v;           // exclusive within chunk
    if (t == 1023) btot[blockIdx.x] = sm[1023];
}
__global__ void scan_b_kernel(int* __restrict__ btot, int nb) {
    if (threadIdx.x == 0 && blockIdx.x == 0) {
        int run = 0;
        for (int b = 0; b < nb; ++b) { int t = btot[b]; btot[b] = run; run += t; }
    }
}
__global__ void scan_c_kernel(int* __restrict__ offs, const int* __restrict__ btot,
                              int* __restrict__ work, int N, int E) {
    int i = blockIdx.x * blockDim.x + threadIdx.x;
    if (i < N) {
        int o = offs[i] + btot[i >> 10];
        offs[i] = o;
        work[i] = o;
    }
    if (i == 0) offs[N] = E;
}
__global__ void scatter_kernel(const int* __restrict__ src, const int* __restrict__ dst,
                               const float* __restrict__ ev, int* __restrict__ work,
                               int* __restrict__ csrc, float* __restrict__ cev, int E) {
    int e = blockIdx.x * blockDim.x + threadIdx.x;
    if (e < E) {
        int p = atomicAdd(&work[dst[e]], 1);
        csrc[p] = src[e];
        cev[p] = ev[e];
    }
}

// ---------------- TF32 HMMA GEMM + attention scalars ---------------------------
#define SB_BH   0
#define SB_BL   67584
#define SB_AH   135168
#define SB_AL   153600
#define SB_RED  172032
#define SMEM_TOT 176128

template <int ACT>
__global__ void __launch_bounds__(256, 1) gemm_mma_kernel(
    const float* __restrict__ x, const float* __restrict__ wt_hi, const float* __restrict__ wt_lo,
    const float* __restrict__ a_src, const float* __restrict__ a_dst,
    float* __restrict__ h, float* __restrict__ ssrc, float* __restrict__ sdst, int N)
{
    extern __shared__ char smem[];
    float* Bh = (float*)(smem + SB_BH);
    float* Bl = (float*)(smem + SB_BL);
    float* Ah = (float*)(smem + SB_AH);
    float* Al = (float*)(smem + SB_AL);
    float* red_s = (float*)(smem + SB_RED);
    float* red_d = red_s + 128 * 4;

    const int tid = threadIdx.x;
    const int lane = tid & 31;
    const int wid = tid >> 5;
    const int wm = wid & 1;
    const int wn = wid >> 1;
    const int r0 = blockIdx.x * 128;

    for (int i = tid; i < 128 * 32; i += 256) {
        int n = i >> 5, kq = i & 31;
        *(float4*)&Bh[n * 132 + kq * 4] = *(const float4*)(wt_hi + n * DIM + kq * 4);
        *(float4*)&Bl[n * 132 + kq * 4] = *(const float4*)(wt_lo + n * DIM + kq * 4);
    }

    float acc[4][4][4];
#pragma unroll
    for (int mt = 0; mt < 4; ++mt)
#pragma unroll
        for (int nt = 0; nt < 4; ++nt)
#pragma unroll
            for (int q = 0; q < 4; ++q) acc[mt][nt][q] = 0.f;

    const int prow = tid >> 1;
    const int pkq0 = (tid & 1) * 4;
    float4 pref[4];
#pragma unroll
    for (int q = 0; q < 4; ++q) {
        pref[q] = make_float4(0.f, 0.f, 0.f, 0.f);
        if (r0 + prow < N)
            pref[q] = *(const float4*)(x + (size_t)(r0 + prow) * DIM + (pkq0 + q) * 4);
    }

    for (int kc = 0; kc < 4; ++kc) {
        __syncthreads();
#pragma unroll
        for (int q = 0; q < 4; ++q) {
            float4 v = pref[q];
            if (ACT) { v.x = elu_f(v.x); v.y = elu_f(v.y); v.z = elu_f(v.z); v.w = elu_f(v.w); }
            float4 hi = make_float4(tf32_rna(v.x), tf32_rna(v.y), tf32_rna(v.z), tf32_rna(v.w));
            float4 lo = make_float4(tf32_rna(v.x - hi.x), tf32_rna(v.y - hi.y),
                                    tf32_rna(v.z - hi.z), tf32_rna(v.w - hi.w));
            *(float4*)&Ah[prow * 36 + (pkq0 + q) * 4] = hi;
            *(float4*)&Al[prow * 36 + (pkq0 + q) * 4] = lo;
        }
        if (kc < 3) {
#pragma unroll
            for (int q = 0; q < 4; ++q) {
                pref[q] = make_float4(0.f, 0.f, 0.f, 0.f);
                if (r0 + prow < N)
                    pref[q] = *(const float4*)(x + (size_t)(r0 + prow) * DIM
                                               + (kc + 1) * 32 + (pkq0 + q) * 4);
            }
        }
        __syncthreads();

        const uint32_t* uAh = (const uint32_t*)Ah;
        const uint32_t* uAl = (const uint32_t*)Al;
        const uint32_t* uBh = (const uint32_t*)Bh;
        const uint32_t* uBl = (const uint32_t*)Bl;

#pragma unroll
        for (int ks = 0; ks < 4; ++ks) {
            const int k0 = ks * 8;
            uint32_t bh[4][2], bl[4][2];
#pragma unroll
            for (int nt = 0; nt < 4; ++nt) {
                int bn = wn * 32 + nt * 8 + (lane >> 2);
                int bk = kc * 32 + k0 + (lane & 3);
                bh[nt][0] = uBh[bn * 132 + bk];
                bh[nt][1] = uBh[bn * 132 + bk + 4];
                bl[nt][0] = uBl[bn * 132 + bk];
                bl[nt][1] = uBl[bn * 132 + bk + 4];
            }
            uint32_t ah[4][4], al[4][4];
#pragma unroll
            for (int mt = 0; mt < 4; ++mt) {
                int ar = wm * 64 + mt * 16 + (lane >> 2);
                int ac = k0 + (lane & 3);
                ah[mt][0] = uAh[ar * 36 + ac];
                ah[mt][1] = uAh[(ar + 8) * 36 + ac];
                ah[mt][2] = uAh[ar * 36 + ac + 4];
                ah[mt][3] = uAh[(ar + 8) * 36 + ac + 4];
                al[mt][0] = uAl[ar * 36 + ac];
                al[mt][1] = uAl[(ar + 8) * 36 + ac];
                al[mt][2] = uAl[ar * 36 + ac + 4];
                al[mt][3] = uAl[(ar + 8) * 36 + ac + 4];
            }
#pragma unroll
            for (int mt = 0; mt < 4; ++mt)
#pragma unroll
                for (int nt = 0; nt < 4; ++nt) {
                    mma_tf32(acc[mt][nt], ah[mt], bh[nt]);
                    mma_tf32(acc[mt][nt], ah[mt], bl[nt]);
                    mma_tf32(acc[mt][nt], al[mt], bh[nt]);
                }
        }
    }

    float asv[4][2], adv[4][2];
#pragma unroll
    for (int nt = 0; nt < 4; ++nt) {
        int c0 = wn * 32 + nt * 8 + 2 * (lane & 3);
        asv[nt][0] = a_src[c0];     asv[nt][1] = a_src[c0 + 1];
        adv[nt][0] = a_dst[c0];     adv[nt][1] = a_dst[c0 + 1];
    }

    float ps[8], pd[8];
#pragma unroll
    for (int q = 0; q < 8; ++q) { ps[q] = 0.f; pd[q] = 0.f; }

#pragma unroll
    for (int mt = 0; mt < 4; ++mt) {
        int ar = r0 + wm * 64 + mt * 16 + (lane >> 2);
#pragma unroll
        for (int nt = 0; nt < 4; ++nt) {
            int c0 = wn * 32 + nt * 8 + 2 * (lane & 3);
            if (ar < N)
                *(float2*)(h + (size_t)ar * DIM + c0) = make_float2(acc[mt][nt][0], acc[mt][nt][1]);
            if (ar + 8 < N)
                *(float2*)(h + (size_t)(ar + 8) * DIM + c0) = make_float2(acc[mt][nt][2], acc[mt][nt][3]);
            ps[mt * 2 + 0] += acc[mt][nt][0] * asv[nt][0] + acc[mt][nt][1] * asv[nt][1];
            ps[mt * 2 + 1] += acc[mt][nt][2] * asv[nt][0] + acc[mt][nt][3] * asv[nt][1];
            pd[mt * 2 + 0] += acc[mt][nt][0] * adv[nt][0] + acc[mt][nt][1] * adv[nt][1];
            pd[mt * 2 + 1] += acc[mt][nt][2] * adv[nt][0] + acc[mt][nt][3] * adv[nt][1];
        }
    }
#pragma unroll
    for (int q = 0; q < 8; ++q) {
        ps[q] += __shfl_xor_sync(0xFFFFFFFF, ps[q], 1);
        ps[q] += __shfl_xor_sync(0xFFFFFFFF, ps[q], 2);
        pd[q] += __shfl_xor_sync(0xFFFFFFFF, pd[q], 1);
        pd[q] += __shfl_xor_sync(0xFFFFFFFF, pd[q], 2);
    }
    __syncthreads();
    if ((lane & 3) == 0) {
#pragma unroll
        for (int mt = 0; mt < 4; ++mt) {
            int rl0 = wm * 64 + mt * 16 + (lane >> 2);
            red_s[rl0 * 4 + wn] = ps[mt * 2 + 0];
            red_s[(rl0 + 8) * 4 + wn] = ps[mt * 2 + 1];
            red_d[rl0 * 4 + wn] = pd[mt * 2 + 0];
            red_d[(rl0 + 8) * 4 + wn] = pd[mt * 2 + 1];
        }
    }
    __syncthreads();
    if (tid < 128) {
        int row = r0 + tid;
        if (row < N) {
            float s = red_s[tid * 4] + red_s[tid * 4 + 1] + red_s[tid * 4 + 2] + red_s[tid * 4 + 3];
            float d = red_d[tid * 4] + red_d[tid * 4 + 1] + red_d[tid * 4 + 2] + red_d[tid * 4 + 3];
            ssrc[row] = s;
            sdst[row] = d;
        }
    }
}

// ---------------- fused CSR aggregate: softmax + weighted sum, no atomics -------
// one warp per dst node; lane owns 4 output columns.
__global__ void agg_csr_kernel(const int* __restrict__ off, const int* __restrict__ csrc,
                               const float* __restrict__ cev,
                               const float* __restrict__ ssrc, const float* __restrict__ sdst,
                               const float* __restrict__ h, float* __restrict__ out, int N)
{
    int warp = (blockIdx.x * blockDim.x + threadIdx.x) >> 5;
    int lane = threadIdx.x & 31;
    if (warp >= N) return;
    const int d = warp;
    const int o0 = off[d], o1 = off[d + 1];
    const float sd = sdst[d];

    float4 acc = make_float4(0.f, 0.f, 0.f, 0.f);
    float denom = 0.f;

    for (int base = o0; base < o1; base += 32) {
        int idx = base + lane;
        float e = 0.f;
        int s = 0;
        if (idx < o1) {
            s = csrc[idx];
            float l = ssrc[s] + sd;
            l = l > 0.f ? l : 0.2f * l;
            e = __expf(l) * cev[idx];
        }
        float esum = e;
#pragma unroll
        for (int m = 16; m; m >>= 1) esum += __shfl_xor_sync(0xFFFFFFFF, esum, m);
        denom += esum;

        int cnt = min(32, o1 - base);
        for (int k = 0; k < cnt; ++k) {
            float coef = __shfl_sync(0xFFFFFFFF, e, k);
            int sk = __shfl_sync(0xFFFFFFFF, s, k);
            float4 v = *(const float4*)(h + (size_t)sk * DIM + lane * 4);
            acc.x += coef * v.x; acc.y += coef * v.y;
            acc.z += coef * v.z; acc.w += coef * v.w;
        }
    }
    float inv = 1.f / (denom + 1e-16f);
    acc.x *= inv; acc.y *= inv; acc.z *= inv; acc.w *= inv;
    *(float4*)(out + (size_t)d * DIM + lane * 4) = acc;
}

// ---------------- final gather (deferred elu applied here) ----------------------
__global__ void gather_kernel(const float* __restrict__ uo, const float* __restrict__ io,
                              const int* __restrict__ uid, const int* __restrict__ iid,
                              float* __restrict__ out)
{
    int t = blockIdx.x * blockDim.x + threadIdx.x;
    int b = t >> 7, c = t & 127;
    if (b < BATCH)          out[t] = elu_f(uo[(size_t)uid[b] * DIM + c]);
    else if (b < 2 * BATCH) out[t] = elu_f(io[(size_t)iid[b - BATCH] * DIM + c]);
}

// ---------------- host orchestration -------------------------------------------
static void build_csr(const int* ei, const float* ev, int E, int N,
                      int* cnt, int* off, int* btot, int* work, int* csrc, float* cev)
{
    const int TB = 256;
    const int* src = ei;
    const int* dst = ei + E;
    int nb = (N + 1023) / 1024;
    zero_cnt_kernel<<<(N + TB) / TB, TB>>>(cnt, N);
    count_kernel<<<(E + TB - 1) / TB, TB>>>(dst, cnt, E);
    scan_a_kernel<<<nb, 1024>>>(cnt, off, btot, N);
    scan_b_kernel<<<1, 32>>>(btot, nb);
    scan_c_kernel<<<(N + TB - 1) / TB, TB>>>(off, btot, work, N, E);
    scatter_kernel<<<(E + TB - 1) / TB, TB>>>(src, dst, ev, work, csrc, cev, E);
}

static void run_layer(const float* x, int act, int N,
                      const float* wt_hi, const float* wt_lo,
                      const float* as, const float* ad,
                      float* h, float* outp, float* ssrc, float* sdst,
                      const int* off, const int* csrc, const float* cev)
{
    if (act)
        gemm_mma_kernel<1><<<(N + 127) / 128, 256, SMEM_TOT>>>(x, wt_hi, wt_lo, as, ad, h, ssrc, sdst, N);
    else
        gemm_mma_kernel<0><<<(N + 127) / 128, 256, SMEM_TOT>>>(x, wt_hi, wt_lo, as, ad, h, ssrc, sdst, N);
    agg_csr_kernel<<<(N + 7) / 8, 256>>>(off, csrc, cev, ssrc, sdst, h, outp, N);
}

extern "C" void kernel_launch(void* const* d_in, const int* in_sizes, int n_in,
                              void* d_out, int out_size)
{
    const int*   uedg = (const int*)d_in[0];
    const int*   iedg = (const int*)d_in[1];
    const int*   user_id = (const int*)d_in[2];
    const int*   item_id = (const int*)d_in[3];
    const float* uval = (const float*)d_in[4];
    const float* ival = (const float*)d_in[5];
    const float* umat = (const float*)d_in[6];
    const float* imat = (const float*)d_in[7];
    const float* W_u1 = (const float*)d_in[8];
    const float* as_u1 = (const float*)d_in[9];
    const float* ad_u1 = (const float*)d_in[10];
    const float* W_u2 = (const float*)d_in[11];
    const float* as_u2 = (const float*)d_in[12];
    const float* ad_u2 = (const float*)d_in[13];
    const float* W_i1 = (const float*)d_in[14];
    const float* as_i1 = (const float*)d_in[15];
    const float* ad_i1 = (const float*)d_in[16];
    const float* W_i2 = (const float*)d_in[17];
    const float* as_i2 = (const float*)d_in[18];
    const float* ad_i2 = (const float*)d_in[19];

    float *h, *out1, *uout2, *iout2, *ssrc, *sdst, *wthi, *wtlo, *cev;
    int *cnt, *off, *btot, *work, *csrc;
    cudaGetSymbolAddress((void**)&h, g_h);
    cudaGetSymbolAddress((void**)&out1, g_out1);
    cudaGetSymbolAddress((void**)&uout2, g_uout2);
    cudaGetSymbolAddress((void**)&iout2, g_iout2);
    cudaGetSymbolAddress((void**)&ssrc, g_ssrc);
    cudaGetSymbolAddress((void**)&sdst, g_sdst);
    cudaGetSymbolAddress((void**)&wthi, g_wt_hi);
    cudaGetSymbolAddress((void**)&wtlo, g_wt_lo);
    cudaGetSymbolAddress((void**)&cnt, g_cnt);
    cudaGetSymbolAddress((void**)&off, g_off);
    cudaGetSymbolAddress((void**)&btot, g_btot);
    cudaGetSymbolAddress((void**)&work, g_work);
    cudaGetSymbolAddress((void**)&csrc, g_csrc);
    cudaGetSymbolAddress((void**)&cev, g_cev);

    cudaFuncSetAttribute(gemm_mma_kernel<0>, cudaFuncAttributeMaxDynamicSharedMemorySize, SMEM_TOT);
    cudaFuncSetAttribute(gemm_mma_kernel<1>, cudaFuncAttributeMaxDynamicSharedMemorySize, SMEM_TOT);

    prep_w_kernel<<<4 * DIM * DIM / 256, 256>>>(W_i1, W_i2, W_u1, W_u2);

    // item graph
    build_csr(iedg, ival, EI, NI, cnt, off, btot, work, csrc, cev);
    run_layer(imat, 0, NI, wthi + 0 * DIM * DIM, wtlo + 0 * DIM * DIM, as_i1, ad_i1,
              h, out1, ssrc, sdst, off, csrc, cev);
    run_layer(out1, 1, NI, wthi + 1 * DIM * DIM, wtlo + 1 * DIM * DIM, as_i2, ad_i2,
              h, iout2, ssrc, sdst, off, csrc, cev);

    // user graph
    build_csr(uedg, uval, EU, NU, cnt, off, btot, work, csrc, cev);
    run_layer(umat, 0, NU, wthi + 2 * DIM * DIM, wtlo + 2 * DIM * DIM, as_u1, ad_u1,
              h, out1, ssrc, sdst, off, csrc, cev);
    run_layer(out1, 1, NU, wthi + 3 * DIM * DIM, wtlo + 3 * DIM * DIM, as_u2, ad_u2,
              h, uout2, ssrc, sdst, off, csrc, cev);

    gather_kernel<<<(2 * BATCH * DIM) / 256, 256>>>(uout2, iout2, user_id, item_id, (float*)d_out);
}

// round 5
// speedup vs baseline: 1.1344x; 1.0205x over previous
#include <cuda_runtime.h>
#include <cstdint>
#include <cfloat>

#define NU 100000
#define NI 50000
#define DIM 128
#define EU 400000
#define EI 200000
#define BATCH 4096

#define NBI_G ((NI + 127) / 128)       // 391 gemm blocks (item)
#define NBU_G ((NU + 127) / 128)       // 782 gemm blocks (user)
#define NBI_SC ((NI + 1023) / 1024)    // 49 scan blocks (item)
#define NBU_SC ((NU + 1023) / 1024)    // 98 scan blocks (user)
#define AB_I ((NI + 7) / 8)            // 6250 agg blocks (item)
#define AB_U ((NU + 7) / 8)            // 12500 agg blocks (user)

// ---------------- scratch (static device memory) ------------------------------
__device__ float g_h_u[NU * DIM];
__device__ float g_h_i[NI * DIM];
__device__ float g_out1_u[NU * DIM];
__device__ float g_out1_i[NI * DIM];
__device__ float g_uout2[NU * DIM];
__device__ float g_iout2[NI * DIM];
__device__ float g_ssrc_u[NU], g_sdst_u[NU];
__device__ float g_ssrc_i[NI], g_sdst_i[NI];
__device__ float g_wt_hi[4][DIM * DIM];
__device__ float g_wt_lo[4][DIM * DIM];
// CSR (both graphs persist)
__device__ int   g_cnt_u[NU + 1], g_cnt_i[NI + 1];
__device__ int   g_off_u[NU + 1], g_off_i[NI + 1];
__device__ int   g_btot_u[NBU_SC], g_btot_i[NBI_SC];
__device__ int   g_work_u[NU], g_work_i[NI];
__device__ int   g_csrc_u[EU], g_csrc_i[EI];
__device__ float g_cev_u[EU],  g_cev_i[EI];

// ---------------- helpers ------------------------------------------------------
__device__ __forceinline__ float elu_f(float x) { return x > 0.f ? x : expm1f(x); }

__device__ __forceinline__ float tf32_rna(float a) {
    uint32_t b; asm("cvt.rna.tf32.f32 %0, %1;" : "=r"(b) : "f"(a));
    return __uint_as_float(b);
}
__device__ __forceinline__ void mma_tf32(float* d, const uint32_t* a, const uint32_t* b) {
    asm volatile(
        "mma.sync.aligned.m16n8k8.row.col.f32.tf32.tf32.f32 "
        "{%0,%1,%2,%3}, {%4,%5,%6,%7}, {%8,%9}, {%0,%1,%2,%3};"
        : "+f"(d[0]), "+f"(d[1]), "+f"(d[2]), "+f"(d[3])
        : "r"(a[0]), "r"(a[1]), "r"(a[2]), "r"(a[3]), "r"(b[0]), "r"(b[1]));
}

// ---------------- W^T hi/lo prep ----------------------------------------------
__global__ void prep_w_kernel(const float* __restrict__ w0, const float* __restrict__ w1,
                              const float* __restrict__ w2, const float* __restrict__ w3) {
    int i = blockIdx.x * blockDim.x + threadIdx.x;
    const float* W = (i < 16384) ? w0 : (i < 32768) ? w1 : (i < 49152) ? w2 : w3;
    int l = i >> 14;
    int j = i & 16383;
    int n = j >> 7, k = j & 127;
    float w = W[k * DIM + n];
    float hi = tf32_rna(w);
    g_wt_hi[l][n * DIM + k] = hi;
    g_wt_lo[l][n * DIM + k] = tf32_rna(w - hi);
}

// ---------------- merged CSR build (both graphs per launch) --------------------
__global__ void zero_cnt_kernel() {
    int i = blockIdx.x * blockDim.x + threadIdx.x;
    if (i <= NU) g_cnt_u[i] = 0;
    if (i <= NI) g_cnt_i[i] = 0;
}
__global__ void count_kernel(const int* __restrict__ udst, const int* __restrict__ idst) {
    int e = blockIdx.x * blockDim.x + threadIdx.x;
    if (e < EU) atomicAdd(&g_cnt_u[udst[e]], 1);
    if (e < EI) atomicAdd(&g_cnt_i[idst[e]], 1);
}
__global__ void __launch_bounds__(1024) scan_a_kernel() {
    __shared__ int sm[1024];
    int t = threadIdx.x;
    int b = blockIdx.x;
    const int* cnt;  int* offs;  int* btot;  int N;  int lb;
    if (b < NBI_SC) { cnt = g_cnt_i; offs = g_off_i; btot = g_btot_i; N = NI; lb = b; }
    else            { cnt = g_cnt_u; offs = g_off_u; btot = g_btot_u; N = NU; lb = b - NBI_SC; }
    int i = lb * 1024 + t;
    int v = (i < N) ? cnt[i] : 0;
    sm[t] = v;
    __syncthreads();
#pragma unroll
    for (int s = 1; s < 1024; s <<= 1) {
        int u = (t >= s) ? sm[t - s] : 0;
        __syncthreads();
        sm[t] += u;
        __syncthreads();
    }
    if (i < N) offs[i] = sm[t] - v;
    if (t == 1023) btot[lb] = sm[1023];
}
__global__ void scan_b_kernel() {
    if (threadIdx.x == 0) {
        int run = 0;
        for (int b = 0; b < NBI_SC; ++b) { int t = g_btot_i[b]; g_btot_i[b] = run; run += t; }
        run = 0;
        for (int b = 0; b < NBU_SC; ++b) { int t = g_btot_u[b]; g_btot_u[b] = run; run += t; }
    }
}
__global__ void scan_c_kernel() {
    int i = blockIdx.x * blockDim.x + threadIdx.x;
    if (i < NI) {
        int o = g_off_i[i] + g_btot_i[i >> 10];
        g_off_i[i] = o;  g_work_i[i] = o;
    }
    if (i < NU) {
        int o = g_off_u[i] + g_btot_u[i >> 10];
        g_off_u[i] = o;  g_work_u[i] = o;
    }
    if (i == 0) { g_off_i[NI] = EI; g_off_u[NU] = EU; }
}
__global__ void scatter_kernel(const int* __restrict__ uedg, const float* __restrict__ uev,
                               const int* __restrict__ iedg, const float* __restrict__ iev) {
    int e = blockIdx.x * blockDim.x + threadIdx.x;
    if (e < EU) {
        int p = atomicAdd(&g_work_u[uedg[EU + e]], 1);
        g_csrc_u[p] = uedg[e];
        g_cev_u[p] = uev[e];
    }
    if (e < EI) {
        int p = atomicAdd(&g_work_i[iedg[EI + e]], 1);
        g_csrc_i[p] = iedg[e];
        g_cev_i[p] = iev[e];
    }
}

// ---------------- merged TF32 HMMA GEMM + attention scalars --------------------
struct GemmArgs {
    const float *x, *wh, *wl, *as, *ad;
    float *h, *ssrc, *sdst;
    int N;
};

#define SB_BH   0
#define SB_BL   67584
#define SB_AH   135168
#define SB_AL   153600
#define SB_RED  172032
#define SMEM_TOT 176128

template <int ACT>
__global__ void __launch_bounds__(256, 1) gemm_mma_kernel(GemmArgs gi, GemmArgs gu)
{
    extern __shared__ char smem[];
    float* Bh = (float*)(smem + SB_BH);
    float* Bl = (float*)(smem + SB_BL);
    float* Ah = (float*)(smem + SB_AH);
    float* Al = (float*)(smem + SB_AL);
    float* red_s = (float*)(smem + SB_RED);
    float* red_d = red_s + 128 * 4;

    const GemmArgs& g = (blockIdx.x < NBI_G) ? gi : gu;
    const int blk = (blockIdx.x < NBI_G) ? blockIdx.x : (blockIdx.x - NBI_G);
    const float* __restrict__ x = g.x;
    const int N = g.N;

    const int tid = threadIdx.x;
    const int lane = tid & 31;
    const int wid = tid >> 5;
    const int wm = wid & 1;
    const int wn = wid >> 1;
    const int r0 = blk * 128;

    for (int i = tid; i < 128 * 32; i += 256) {
        int n = i >> 5, kq = i & 31;
        *(float4*)&Bh[n * 132 + kq * 4] = *(const float4*)(g.wh + n * DIM + kq * 4);
        *(float4*)&Bl[n * 132 + kq * 4] = *(const float4*)(g.wl + n * DIM + kq * 4);
    }

    float acc[4][4][4];
#pragma unroll
    for (int mt = 0; mt < 4; ++mt)
#pragma unroll
        for (int nt = 0; nt < 4; ++nt)
#pragma unroll
            for (int q = 0; q < 4; ++q) acc[mt][nt][q] = 0.f;

    const int prow = tid >> 1;
    const int pkq0 = (tid & 1) * 4;
    float4 pref[4];
#pragma unroll
    for (int q = 0; q < 4; ++q) {
        pref[q] = make_float4(0.f, 0.f, 0.f, 0.f);
        if (r0 + prow < N)
            pref[q] = *(const float4*)(x + (size_t)(r0 + prow) * DIM + (pkq0 + q) * 4);
    }

    for (int kc = 0; kc < 4; ++kc) {
        __syncthreads();
#pragma unroll
        for (int q = 0; q < 4; ++q) {
            float4 v = pref[q];
            if (ACT) { v.x = elu_f(v.x); v.y = elu_f(v.y); v.z = elu_f(v.z); v.w = elu_f(v.w); }
            float4 hi = make_float4(tf32_rna(v.x), tf32_rna(v.y), tf32_rna(v.z), tf32_rna(v.w));
            float4 lo = make_float4(tf32_rna(v.x - hi.x), tf32_rna(v.y - hi.y),
                                    tf32_rna(v.z - hi.z), tf32_rna(v.w - hi.w));
            *(float4*)&Ah[prow * 36 + (pkq0 + q) * 4] = hi;
            *(float4*)&Al[prow * 36 + (pkq0 + q) * 4] = lo;
        }
        if (kc < 3) {
#pragma unroll
            for (int q = 0; q < 4; ++q) {
                pref[q] = make_float4(0.f, 0.f, 0.f, 0.f);
                if (r0 + prow < N)
                    pref[q] = *(const float4*)(x + (size_t)(r0 + prow) * DIM
                                               + (kc + 1) * 32 + (pkq0 + q) * 4);
            }
        }
        __syncthreads();

        const uint32_t* uAh = (const uint32_t*)Ah;
        const uint32_t* uAl = (const uint32_t*)Al;
        const uint32_t* uBh = (const uint32_t*)Bh;
        const uint32_t* uBl = (const uint32_t*)Bl;

#pragma unroll
        for (int ks = 0; ks < 4; ++ks) {
            const int k0 = ks * 8;
            uint32_t bh[4][2], bl[4][2];
#pragma unroll
            for (int nt = 0; nt < 4; ++nt) {
                int bn = wn * 32 + nt * 8 + (lane >> 2);
                int bk = kc * 32 + k0 + (lane & 3);
                bh[nt][0] = uBh[bn * 132 + bk];
                bh[nt][1] = uBh[bn * 132 + bk + 4];
                bl[nt][0] = uBl[bn * 132 + bk];
                bl[nt][1] = uBl[bn * 132 + bk + 4];
            }
            uint32_t ah[4][4], al[4][4];
#pragma unroll
            for (int mt = 0; mt < 4; ++mt) {
                int ar = wm * 64 + mt * 16 + (lane >> 2);
                int ac = k0 + (lane & 3);
                ah[mt][0] = uAh[ar * 36 + ac];
                ah[mt][1] = uAh[(ar + 8) * 36 + ac];
                ah[mt][2] = uAh[ar * 36 + ac + 4];
                ah[mt][3] = uAh[(ar + 8) * 36 + ac + 4];
                al[mt][0] = uAl[ar * 36 + ac];
                al[mt][1] = uAl[(ar + 8) * 36 + ac];
                al[mt][2] = uAl[ar * 36 + ac + 4];
                al[mt][3] = uAl[(ar + 8) * 36 + ac + 4];
            }
#pragma unroll
            for (int mt = 0; mt < 4; ++mt)
#pragma unroll
                for (int nt = 0; nt < 4; ++nt) {
                    mma_tf32(acc[mt][nt], ah[mt], bh[nt]);
                    mma_tf32(acc[mt][nt], ah[mt], bl[nt]);
                    mma_tf32(acc[mt][nt], al[mt], bh[nt]);
                }
        }
    }

    float asv[4][2], adv[4][2];
#pragma unroll
    for (int nt = 0; nt < 4; ++nt) {
        int c0 = wn * 32 + nt * 8 + 2 * (lane & 3);
        asv[nt][0] = g.as[c0];   asv[nt][1] = g.as[c0 + 1];
        adv[nt][0] = g.ad[c0];   adv[nt][1] = g.ad[c0 + 1];
    }

    float ps[8], pd[8];
#pragma unroll
    for (int q = 0; q < 8; ++q) { ps[q] = 0.f; pd[q] = 0.f; }

    float* __restrict__ h = g.h;
#pragma unroll
    for (int mt = 0; mt < 4; ++mt) {
        int ar = r0 + wm * 64 + mt * 16 + (lane >> 2);
#pragma unroll
        for (int nt = 0; nt < 4; ++nt) {
            int c0 = wn * 32 + nt * 8 + 2 * (lane & 3);
            if (ar < N)
                *(float2*)(h + (size_t)ar * DIM + c0) = make_float2(acc[mt][nt][0], acc[mt][nt][1]);
            if (ar + 8 < N)
                *(float2*)(h + (size_t)(ar + 8) * DIM + c0) = make_float2(acc[mt][nt][2], acc[mt][nt][3]);
            ps[mt * 2 + 0] += acc[mt][nt][0] * asv[nt][0] + acc[mt][nt][1] * asv[nt][1];
            ps[mt * 2 + 1] += acc[mt][nt][2] * asv[nt][0] + acc[mt][nt][3] * asv[nt][1];
            pd[mt * 2 + 0] += acc[mt][nt][0] * adv[nt][0] + acc[mt][nt][1] * adv[nt][1];
            pd[mt * 2 + 1] += acc[mt][nt][2] * adv[nt][0] + acc[mt][nt][3] * adv[nt][1];
        }
    }
#pragma unroll
    for (int q = 0; q < 8; ++q) {
        ps[q] += __shfl_xor_sync(0xFFFFFFFF, ps[q], 1);
        ps[q] += __shfl_xor_sync(0xFFFFFFFF, ps[q], 2);
        pd[q] += __shfl_xor_sync(0xFFFFFFFF, pd[q], 1);
        pd[q] += __shfl_xor_sync(0xFFFFFFFF, pd[q], 2);
    }
    __syncthreads();
    if ((lane & 3) == 0) {
#pragma unroll
        for (int mt = 0; mt < 4; ++mt) {
            int rl0 = wm * 64 + mt * 16 + (lane >> 2);
            red_s[rl0 * 4 + wn] = ps[mt * 2 + 0];
            red_s[(rl0 + 8) * 4 + wn] = ps[mt * 2 + 1];
            red_d[rl0 * 4 + wn] = pd[mt * 2 + 0];
            red_d[(rl0 + 8) * 4 + wn] = pd[mt * 2 + 1];
        }
    }
    __syncthreads();
    if (tid < 128) {
        int row = r0 + tid;
        if (row < N) {
            float s = red_s[tid * 4] + red_s[tid * 4 + 1] + red_s[tid * 4 + 2] + red_s[tid * 4 + 3];
            float d = red_d[tid * 4] + red_d[tid * 4 + 1] + red_d[tid * 4 + 2] + red_d[tid * 4 + 3];
            g.ssrc[row] = s;
            g.sdst[row] = d;
        }
    }
}

// ---------------- merged CSR aggregate (both graphs per launch) ----------------
struct AggArgs {
    const int* off;
    const int* csrc;
    const float* cev;
    const float *ssrc, *sdst, *h;
    float* out;
    int N;
};

__global__ void agg_csr_kernel(AggArgs ai, AggArgs au)
{
    const AggArgs& a = (blockIdx.x < AB_I) ? ai : au;
    const int blk = (blockIdx.x < AB_I) ? blockIdx.x : (blockIdx.x - AB_I);
    int lane = threadIdx.x & 31;
    int d = blk * 8 + (threadIdx.x >> 5);
    if (d >= a.N) return;
    const int o0 = a.off[d], o1 = a.off[d + 1];
    const float sd = a.sdst[d];
    const float* __restrict__ h = a.h;

    float4 acc = make_float4(0.f, 0.f, 0.f, 0.f);
    float denom = 0.f;

    for (int base = o0; base < o1; base += 32) {
        int idx = base + lane;
        float e = 0.f;
        int s = 0;
        if (idx < o1) {
            s = a.csrc[idx];
            float l = a.ssrc[s] + sd;
            l = l > 0.f ? l : 0.2f * l;
            e = __expf(l) * a.cev[idx];
        }
        float esum = e;
#pragma unroll
        for (int m = 16; m; m >>= 1) esum += __shfl_xor_sync(0xFFFFFFFF, esum, m);
        denom += esum;

        int cnt = min(32, o1 - base);
        for (int k = 0; k < cnt; ++k) {
            float coef = __shfl_sync(0xFFFFFFFF, e, k);
            int sk = __shfl_sync(0xFFFFFFFF, s, k);
            float4 v = *(const float4*)(h + (size_t)sk * DIM + lane * 4);
            acc.x += coef * v.x; acc.y += coef * v.y;
            acc.z += coef * v.z; acc.w += coef * v.w;
        }
    }
    float inv = 1.f / (denom + 1e-16f);
    acc.x *= inv; acc.y *= inv; acc.z *= inv; acc.w *= inv;
    *(float4*)(a.out + (size_t)d * DIM + lane * 4) = acc;
}

// ---------------- final gather (deferred elu applied here) ----------------------
__global__ void gather_kernel(const float* __restrict__ uo, const float* __restrict__ io,
                              const int* __restrict__ uid, const int* __restrict__ iid,
                              float* __restrict__ out)
{
    int t = blockIdx.x * blockDim.x + threadIdx.x;
    int b = t >> 7, c = t & 127;
    if (b < BATCH)          out[t] = elu_f(uo[(size_t)uid[b] * DIM + c]);
    else if (b < 2 * BATCH) out[t] = elu_f(io[(size_t)iid[b - BATCH] * DIM + c]);
}

// ---------------- host orchestration -------------------------------------------
extern "C" void kernel_launch(void* const* d_in, const int* in_sizes, int n_in,
                              void* d_out, int out_size)
{
    const int*   uedg = (const int*)d_in[0];
    const int*   iedg = (const int*)d_in[1];
    const int*   user_id = (const int*)d_in[2];
    const int*   item_id = (const int*)d_in[3];
    const float* uval = (const float*)d_in[4];
    const float* ival = (const float*)d_in[5];
    const float* umat = (const float*)d_in[6];
    const float* imat = (const float*)d_in[7];
    const float* W_u1 = (const float*)d_in[8];
    const float* as_u1 = (const float*)d_in[9];
    const float* ad_u1 = (const float*)d_in[10];
    const float* W_u2 = (const float*)d_in[11];
    const float* as_u2 = (const float*)d_in[12];
    const float* ad_u2 = (const float*)d_in[13];
    const float* W_i1 = (const float*)d_in[14];
    const float* as_i1 = (const float*)d_in[15];
    const float* ad_i1 = (const float*)d_in[16];
    const float* W_i2 = (const float*)d_in[17];
    const float* as_i2 = (const float*)d_in[18];
    const float* ad_i2 = (const float*)d_in[19];

    float *h_u, *h_i, *out1_u, *out1_i, *uout2, *iout2;
    float *ssrc_u, *sdst_u, *ssrc_i, *sdst_i, *wthi, *wtlo, *cev_u, *cev_i;
    int *off_u, *off_i, *csrc_u, *csrc_i;
    cudaGetSymbolAddress((void**)&h_u, g_h_u);
    cudaGetSymbolAddress((void**)&h_i, g_h_i);
    cudaGetSymbolAddress((void**)&out1_u, g_out1_u);
    cudaGetSymbolAddress((void**)&out1_i, g_out1_i);
    cudaGetSymbolAddress((void**)&uout2, g_uout2);
    cudaGetSymbolAddress((void**)&iout2, g_iout2);
    cudaGetSymbolAddress((void**)&ssrc_u, g_ssrc_u);
    cudaGetSymbolAddress((void**)&sdst_u, g_sdst_u);
    cudaGetSymbolAddress((void**)&ssrc_i, g_ssrc_i);
    cudaGetSymbolAddress((void**)&sdst_i, g_sdst_i);
    cudaGetSymbolAddress((void**)&wthi, g_wt_hi);
    cudaGetSymbolAddress((void**)&wtlo, g_wt_lo);
    cudaGetSymbolAddress((void**)&off_u, g_off_u);
    cudaGetSymbolAddress((void**)&off_i, g_off_i);
    cudaGetSymbolAddress((void**)&csrc_u, g_csrc_u);
    cudaGetSymbolAddress((void**)&csrc_i, g_csrc_i);
    cudaGetSymbolAddress((void**)&cev_u, g_cev_u);
    cudaGetSymbolAddress((void**)&cev_i, g_cev_i);

    cudaFuncSetAttribute(gemm_mma_kernel<0>, cudaFuncAttributeMaxDynamicSharedMemorySize, SMEM_TOT);
    cudaFuncSetAttribute(gemm_mma_kernel<1>, cudaFuncAttributeMaxDynamicSharedMemorySize, SMEM_TOT);

    const int TB = 256;

    // weight prep (layer order: 0=i1, 1=i2, 2=u1, 3=u2)
    prep_w_kernel<<<4 * DIM * DIM / TB, TB>>>(W_i1, W_i2, W_u1, W_u2);

    // merged CSR build for both graphs
    zero_cnt_kernel<<<(NU + TB) / TB, TB>>>();
    count_kernel<<<(EU + TB - 1) / TB, TB>>>(uedg + EU, iedg + EI);
    scan_a_kernel<<<NBI_SC + NBU_SC, 1024>>>();
    scan_b_kernel<<<1, 32>>>();
    scan_c_kernel<<<(NU + TB - 1) / TB, TB>>>();
    scatter_kernel<<<(EU + TB - 1) / TB, TB>>>(uedg, uval, iedg, ival);

    // ---- layer 1 (both graphs merged) ----
    GemmArgs gi1 = { imat, wthi + 0 * DIM * DIM, wtlo + 0 * DIM * DIM, as_i1, ad_i1,
                     h_i, ssrc_i, sdst_i, NI };
    GemmArgs gu1 = { umat, wthi + 2 * DIM * DIM, wtlo + 2 * DIM * DIM, as_u1, ad_u1,
                     h_u, ssrc_u, sdst_u, NU };
    gemm_mma_kernel<0><<<NBI_G + NBU_G, 256, SMEM_TOT>>>(gi1, gu1);

    AggArgs ai1 = { off_i, csrc_i, cev_i, ssrc_i, sdst_i, h_i, out1_i, NI };
    AggArgs au1 = { off_u, csrc_u, cev_u, ssrc_u, sdst_u, h_u, out1_u, NU };
    agg_csr_kernel<<<AB_I + AB_U, 256>>>(ai1, au1);

    // ---- layer 2 (both graphs merged) ----
    GemmArgs gi2 = { out1_i, wthi + 1 * DIM * DIM, wtlo + 1 * DIM * DIM, as_i2, ad_i2,
                     h_i, ssrc_i, sdst_i, NI };
    GemmArgs gu2 = { out1_u, wthi + 3 * DIM * DIM, wtlo + 3 * DIM * DIM, as_u2, ad_u2,
                     h_u, ssrc_u, sdst_u, NU };
    gemm_mma_kernel<1><<<NBI_G + NBU_G, 256, SMEM_TOT>>>(gi2, gu2);

    AggArgs ai2 = { off_i, csrc_i, cev_i, ssrc_i, sdst_i, h_i, iout2, NI };
    AggArgs au2 = { off_u, csrc_u, cev_u, ssrc_u, sdst_u, h_u, uout2, NU };
    agg_csr_kernel<<<AB_I + AB_U, 256>>>(ai2, au2);

    gather_kernel<<<(2 * BATCH * DIM) / TB, TB>>>(uout2, iout2, user_id, item_id, (float*)d_out);
}

// round 7
// speedup vs baseline: 1.2784x; 1.1269x over previous
#include <cuda_runtime.h>
#include <cuda_bf16.h>
#include <cstdint>
#include <cfloat>

#define NU 100000
#define NI 50000
#define DIM 128
#define EU 400000
#define EI 200000
#define BATCH 4096

#define NBI_G ((NI + 127) / 128)       // 391 gemm blocks (item)
#define NBU_G ((NU + 127) / 128)       // 782 gemm blocks (user)
#define NBI_SC ((NI + 1023) / 1024)    // 49 scan blocks (item)
#define NBU_SC ((NU + 1023) / 1024)    // 98 scan blocks (user)
#define AB_I ((NI + 7) / 8)            // agg blocks (item)
#define AB_U ((NU + 7) / 8)            // agg blocks (user)

// ---------------- scratch (static device memory) ------------------------------
__device__ float g_h_u[NU * DIM];
__device__ float g_h_i[NI * DIM];
__device__ float g_out1_u[NU * DIM];
__device__ float g_out1_i[NI * DIM];
__device__ float g_uout2[NU * DIM];
__device__ float g_iout2[NI * DIM];
__device__ float g_ssrc_u[NU], g_sdst_u[NU];
__device__ float g_ssrc_i[NI], g_sdst_i[NI];
__device__ uint32_t g_wp_hi[4][DIM * 64];   // W^T [n][k-pair] bf16x2, hi part
__device__ uint32_t g_wp_lo[4][DIM * 64];   // residual lo part
// CSR (both graphs persist)
__device__ int   g_cnt_u[NU + 1], g_cnt_i[NI + 1];
__device__ int   g_off_u[NU + 1], g_off_i[NI + 1];
__device__ int   g_btot_u[NBU_SC], g_btot_i[NBI_SC];
__device__ int   g_work_u[NU], g_work_i[NI];
__device__ int   g_csrc_u[EU], g_csrc_i[EI];
__device__ float g_cev_u[EU],  g_cev_i[EI];

// ---------------- helpers ------------------------------------------------------
__device__ __forceinline__ float elu_f(float x) { return x > 0.f ? x : expm1f(x); }

__device__ __forceinline__ uint32_t pack_bf2(__nv_bfloat16 a, __nv_bfloat16 b) {
    return ((uint32_t)__bfloat16_as_ushort(b) << 16) | (uint32_t)__bfloat16_as_ushort(a);
}
__device__ __forceinline__ void mma_bf16(float* d, const uint32_t* a, const uint32_t* b) {
    asm volatile(
        "mma.sync.aligned.m16n8k16.row.col.f32.bf16.bf16.f32 "
        "{%0,%1,%2,%3}, {%4,%5,%6,%7}, {%8,%9}, {%0,%1,%2,%3};"
        : "+f"(d[0]), "+f"(d[1]), "+f"(d[2]), "+f"(d[3])
        : "r"(a[0]), "r"(a[1]), "r"(a[2]), "r"(a[3]), "r"(b[0]), "r"(b[1]));
}

// ---------------- W^T hi/lo prep (bf16 split, packed pairs) --------------------
__global__ void prep_w_kernel(const float* __restrict__ w0, const float* __restrict__ w1,
                              const float* __restrict__ w2, const float* __restrict__ w3) {
    int i = blockIdx.x * blockDim.x + threadIdx.x;     // 4*128*64
    int l = i >> 13;
    int j = i & 8191;
    int n = j >> 6, kk = j & 63;
    const float* W = (l == 0) ? w0 : (l == 1) ? w1 : (l == 2) ? w2 : w3;
    float a = W[(2 * kk) * DIM + n];
    float b = W[(2 * kk + 1) * DIM + n];
    __nv_bfloat16 ha = __float2bfloat16(a);
    __nv_bfloat16 hb = __float2bfloat16(b);
    __nv_bfloat16 la = __float2bfloat16(a - __bfloat162float(ha));
    __nv_bfloat16 lb = __float2bfloat16(b - __bfloat162float(hb));
    g_wp_hi[l][n * 64 + kk] = pack_bf2(ha, hb);
    g_wp_lo[l][n * 64 + kk] = pack_bf2(la, lb);
}

// ---------------- merged CSR build (both graphs per launch) --------------------
__global__ void zero_cnt_kernel() {
    int i = blockIdx.x * blockDim.x + threadIdx.x;
    if (i <= NU) g_cnt_u[i] = 0;
    if (i <= NI) g_cnt_i[i] = 0;
}
__global__ void count_kernel(const int* __restrict__ udst, const int* __restrict__ idst) {
    int e = blockIdx.x * blockDim.x + threadIdx.x;
    if (e < EU) atomicAdd(&g_cnt_u[udst[e]], 1);
    if (e < EI) atomicAdd(&g_cnt_i[idst[e]], 1);
}
__global__ void __launch_bounds__(1024) scan_a_kernel() {
    __shared__ int sm[1024];
    int t = threadIdx.x;
    int b = blockIdx.x;
    const int* cnt;  int* offs;  int* btot;  int N;  int lb;
    if (b < NBI_SC) { cnt = g_cnt_i; offs = g_off_i; btot = g_btot_i; N = NI; lb = b; }
    else            { cnt = g_cnt_u; offs = g_off_u; btot = g_btot_u; N = NU; lb = b - NBI_SC; }
    int i = lb * 1024 + t;
    int v = (i < N) ? cnt[i] : 0;
    sm[t] = v;
    __syncthreads();
#pragma unroll
    for (int s = 1; s < 1024; s <<= 1) {
        int u = (t >= s) ? sm[t - s] : 0;
        __syncthreads();
        sm[t] += u;
        __syncthreads();
    }
    if (i < N) offs[i] = sm[t] - v;
    if (t == 1023) btot[lb] = sm[1023];
}
__global__ void scan_b_kernel() {
    if (threadIdx.x == 0) {
        int run = 0;
        for (int b = 0; b < NBI_SC; ++b) { int t = g_btot_i[b]; g_btot_i[b] = run; run += t; }
        run = 0;
        for (int b = 0; b < NBU_SC; ++b) { int t = g_btot_u[b]; g_btot_u[b] = run; run += t; }
    }
}
__global__ void scan_c_kernel() {
    int i = blockIdx.x * blockDim.x + threadIdx.x;
    if (i < NI) {
        int o = g_off_i[i] + g_btot_i[i >> 10];
        g_off_i[i] = o;  g_work_i[i] = o;
    }
    if (i < NU) {
        int o = g_off_u[i] + g_btot_u[i >> 10];
        g_off_u[i] = o;  g_work_u[i] = o;
    }
    if (i == 0) { g_off_i[NI] = EI; g_off_u[NU] = EU; }
}
__global__ void scatter_kernel(const int* __restrict__ uedg, const float* __restrict__ uev,
                               const int* __restrict__ iedg, const float* __restrict__ iev) {
    int e = blockIdx.x * blockDim.x + threadIdx.x;
    if (e < EU) {
        int p = atomicAdd(&g_work_u[uedg[EU + e]], 1);
        g_csrc_u[p] = uedg[e];
        g_cev_u[p] = uev[e];
    }
    if (e < EI) {
        int p = atomicAdd(&g_work_i[iedg[EI + e]], 1);
        g_csrc_i[p] = iedg[e];
        g_cev_i[p] = iev[e];
    }
}

// ---------------- merged BF16 3-term HMMA GEMM + attention scalars -------------
struct GemmArgs {
    const float* x;
    const uint32_t *wh, *wl;
    const float *as, *ad;
    float *h, *ssrc, *sdst;
    int N;
};

// smem (bytes): B hi/lo [128n][68 u32], A hi/lo [128r][68 u32], red buf
#define SB_BH   0
#define SB_BL   34816
#define SB_AH   69632
#define SB_AL   104448
#define SB_RED  139264
#define SMEM_TOT 143360

template <int ACT>
__global__ void __launch_bounds__(256, 1) gemm_mma_kernel(GemmArgs gi, GemmArgs gu)
{
    extern __shared__ char smem[];
    uint32_t* Bh = (uint32_t*)(smem + SB_BH);
    uint32_t* Bl = (uint32_t*)(smem + SB_BL);
    uint32_t* Ah = (uint32_t*)(smem + SB_AH);
    uint32_t* Al = (uint32_t*)(smem + SB_AL);
    float* red_s = (float*)(smem + SB_RED);
    float* red_d = red_s + 128 * 4;

    const GemmArgs& g = (blockIdx.x < NBI_G) ? gi : gu;
    const int blk = (blockIdx.x < NBI_G) ? blockIdx.x : (blockIdx.x - NBI_G);
    const float* __restrict__ x = g.x;
    const int N = g.N;

    const int tid = threadIdx.x;
    const int lane = tid & 31;
    const int wid = tid >> 5;
    const int wm = wid & 1;
    const int wn = wid >> 1;
    const int r0 = blk * 128;

    // stage B (both hi and lo), uint4 copies into stride-68 layout
    for (int i = tid; i < 2048; i += 256) {
        int n = i >> 4, k4 = (i & 15) * 4;
        *(uint4*)&Bh[n * 68 + k4] = *(const uint4*)&g.wh[n * 64 + k4];
        *(uint4*)&Bl[n * 68 + k4] = *(const uint4*)&g.wl[n * 64 + k4];
    }

    // stage full A tile (128 rows x 128 k) with ELU + bf16 hi/lo split
    {
        const int r = tid >> 1;
        const int half = tid & 1;
        const bool ok = (r0 + r < N);
        const float* xr = x + (size_t)(r0 + r) * DIM + half * 64;
#pragma unroll
        for (int q = 0; q < 16; ++q) {
            float4 v = ok ? *(const float4*)(xr + q * 4) : make_float4(0.f, 0.f, 0.f, 0.f);
            if (ACT) { v.x = elu_f(v.x); v.y = elu_f(v.y); v.z = elu_f(v.z); v.w = elu_f(v.w); }
            __nv_bfloat16 hx = __float2bfloat16(v.x), hy = __float2bfloat16(v.y);
            __nv_bfloat16 hz = __float2bfloat16(v.z), hw = __float2bfloat16(v.w);
            __nv_bfloat16 lx = __float2bfloat16(v.x - __bfloat162float(hx));
            __nv_bfloat16 ly = __float2bfloat16(v.y - __bfloat162float(hy));
            __nv_bfloat16 lz = __float2bfloat16(v.z - __bfloat162float(hz));
            __nv_bfloat16 lw = __float2bfloat16(v.w - __bfloat162float(hw));
            int o = r * 68 + half * 32 + q * 2;
            Ah[o] = pack_bf2(hx, hy);  Ah[o + 1] = pack_bf2(hz, hw);
            Al[o] = pack_bf2(lx, ly);  Al[o + 1] = pack_bf2(lz, lw);
        }
    }
    __syncthreads();

    float acc[4][4][4];
#pragma unroll
    for (int mt = 0; mt < 4; ++mt)
#pragma unroll
        for (int nt = 0; nt < 4; ++nt)
#pragma unroll
            for (int q = 0; q < 4; ++q) acc[mt][nt][q] = 0.f;

#pragma unroll
    for (int ks = 0; ks < 8; ++ks) {
        const int kk0 = ks * 8;
        uint32_t bh[4][2], bl[4][2];
#pragma unroll
        for (int nt = 0; nt < 4; ++nt) {
            int bn = wn * 32 + nt * 8 + (lane >> 2);
            bh[nt][0] = Bh[bn * 68 + kk0 + (lane & 3)];
            bh[nt][1] = Bh[bn * 68 + kk0 + 4 + (lane & 3)];
            bl[nt][0] = Bl[bn * 68 + kk0 + (lane & 3)];
            bl[nt][1] = Bl[bn * 68 + kk0 + 4 + (lane & 3)];
        }
        uint32_t ah[4][4], al[4][4];
#pragma unroll
        for (int mt = 0; mt < 4; ++mt) {
            int ar = wm * 64 + mt * 16 + (lane >> 2);
            ah[mt][0] = Ah[ar * 68 + kk0 + (lane & 3)];
            ah[mt][1] = Ah[(ar + 8) * 68 + kk0 + (lane & 3)];
            ah[mt][2] = Ah[ar * 68 + kk0 + 4 + (lane & 3)];
            ah[mt][3] = Ah[(ar + 8) * 68 + kk0 + 4 + (lane & 3)];
            al[mt][0] = Al[ar * 68 + kk0 + (lane & 3)];
            al[mt][1] = Al[(ar + 8) * 68 + kk0 + (lane & 3)];
            al[mt][2] = Al[ar * 68 + kk0 + 4 + (lane & 3)];
            al[mt][3] = Al[(ar + 8) * 68 + kk0 + 4 + (lane & 3)];
        }
#pragma unroll
        for (int mt = 0; mt < 4; ++mt)
#pragma unroll
            for (int nt = 0; nt < 4; ++nt) {
                mma_bf16(acc[mt][nt], ah[mt], bh[nt]);
                mma_bf16(acc[mt][nt], ah[mt], bl[nt]);
                mma_bf16(acc[mt][nt], al[mt], bh[nt]);
            }
    }

    // ---------------- epilogue: store h + attention scalar dots ----------------
    float asv[4][2], adv[4][2];
#pragma unroll
    for (int nt = 0; nt < 4; ++nt) {
        int c0 = wn * 32 + nt * 8 + 2 * (lane & 3);
        asv[nt][0] = g.as[c0];   asv[nt][1] = g.as[c0 + 1];
        adv[nt][0] = g.ad[c0];   adv[nt][1] = g.ad[c0 + 1];
    }

    float ps[8], pd[8];
#pragma unroll
    for (int q = 0; q < 8; ++q) { ps[q] = 0.f; pd[q] = 0.f; }

    float* __restrict__ h = g.h;
#pragma unroll
    for (int mt = 0; mt < 4; ++mt) {
        int ar = r0 + wm * 64 + mt * 16 + (lane >> 2);
#pragma unroll
        for (int nt = 0; nt < 4; ++nt) {
            int c0 = wn * 32 + nt * 8 + 2 * (lane & 3);
            if (ar < N)
                *(float2*)(h + (size_t)ar * DIM + c0) = make_float2(acc[mt][nt][0], acc[mt][nt][1]);
            if (ar + 8 < N)
                *(float2*)(h + (size_t)(ar + 8) * DIM + c0) = make_float2(acc[mt][nt][2], acc[mt][nt][3]);
            ps[mt * 2 + 0] += acc[mt][nt][0] * asv[nt][0] + acc[mt][nt][1] * asv[nt][1];
            ps[mt * 2 + 1] += acc[mt][nt][2] * asv[nt][0] + acc[mt][nt][3] * asv[nt][1];
            pd[mt * 2 + 0] += acc[mt][nt][0] * adv[nt][0] + acc[mt][nt][1] * adv[nt][1];
            pd[mt * 2 + 1] += acc[mt][nt][2] * adv[nt][0] + acc[mt][nt][3] * adv[nt][1];
        }
    }
#pragma unroll
    for (int q = 0; q < 8; ++q) {
        ps[q] += __shfl_xor_sync(0xFFFFFFFF, ps[q], 1);
        ps[q] += __shfl_xor_sync(0xFFFFFFFF, ps[q], 2);
        pd[q] += __shfl_xor_sync(0xFFFFFFFF, pd[q], 1);
        pd[q] += __shfl_xor_sync(0xFFFFFFFF, pd[q], 2);
    }
    __syncthreads();
    if ((lane & 3) == 0) {
#pragma unroll
        for (int mt = 0; mt < 4; ++mt) {
            int rl0 = wm * 64 + mt * 16 + (lane >> 2);
            red_s[rl0 * 4 + wn] = ps[mt * 2 + 0];
            red_s[(rl0 + 8) * 4 + wn] = ps[mt * 2 + 1];
            red_d[rl0 * 4 + wn] = pd[mt * 2 + 0];
            red_d[(rl0 + 8) * 4 + wn] = pd[mt * 2 + 1];
        }
    }
    __syncthreads();
    if (tid < 128) {
        int row = r0 + tid;
        if (row < N) {
            float s = red_s[tid * 4] + red_s[tid * 4 + 1] + red_s[tid * 4 + 2] + red_s[tid * 4 + 3];
            float d = red_d[tid * 4] + red_d[tid * 4 + 1] + red_d[tid * 4 + 2] + red_d[tid * 4 + 3];
            g.ssrc[row] = s;
            g.sdst[row] = d;
        }
    }
}

// ---------------- merged CSR aggregate (both graphs per launch) ----------------
struct AggArgs {
    const int* off;
    const int* csrc;
    const float* cev;
    const float *ssrc, *sdst, *h;
    float* out;
    int N;
};

__global__ void agg_csr_kernel(AggArgs ai, AggArgs au)
{
    const AggArgs& a = (blockIdx.x < AB_I) ? ai : au;
    const int blk = (blockIdx.x < AB_I) ? blockIdx.x : (blockIdx.x - AB_I);
    int lane = threadIdx.x & 31;
    int d = blk * 8 + (threadIdx.x >> 5);
    if (d >= a.N) return;
    const int o0 = a.off[d], o1 = a.off[d + 1];
    const float sd = a.sdst[d];
    const float* __restrict__ h = a.h;

    float4 acc = make_float4(0.f, 0.f, 0.f, 0.f);
    float denom = 0.f;

    for (int base = o0; base < o1; base += 32) {
        int idx = base + lane;
        float e = 0.f;
        int s = 0;
        if (idx < o1) {
            s = a.csrc[idx];
            float l = a.ssrc[s] + sd;
            l = l > 0.f ? l : 0.2f * l;
            e = __expf(l) * a.cev[idx];
        }
        float esum = e;
#pragma unroll
        for (int m = 16; m; m >>= 1) esum += __shfl_xor_sync(0xFFFFFFFF, esum, m);
        denom += esum;

        int cnt = min(32, o1 - base);
        for (int k = 0; k < cnt; ++k) {
            float coef = __shfl_sync(0xFFFFFFFF, e, k);
            int sk = __shfl_sync(0xFFFFFFFF, s, k);
            float4 v = *(const float4*)(h + (size_t)sk * DIM + lane * 4);
            acc.x += coef * v.x; acc.y += coef * v.y;
            acc.z += coef * v.z; acc.w += coef * v.w;
        }
    }
    float inv = 1.f / (denom + 1e-16f);
    acc.x *= inv; acc.y *= inv; acc.z *= inv; acc.w *= inv;
    *(float4*)(a.out + (size_t)d * DIM + lane * 4) = acc;
}

// ---------------- final gather (deferred elu applied here) ----------------------
__global__ void gather_kernel(const float* __restrict__ uo, const float* __restrict__ io,
                              const int* __restrict__ uid, const int* __restrict__ iid,
                              float* __restrict__ out)
{
    int t = blockIdx.x * blockDim.x + threadIdx.x;
    int b = t >> 7, c = t & 127;
    if (b < BATCH)          out[t] = elu_f(uo[(size_t)uid[b] * DIM + c]);
    else if (b < 2 * BATCH) out[t] = elu_f(io[(size_t)iid[b - BATCH] * DIM + c]);
}

// ---------------- host orchestration -------------------------------------------
extern "C" void kernel_launch(void* const* d_in, const int* in_sizes, int n_in,
                              void* d_out, int out_size)
{
    const int*   uedg = (const int*)d_in[0];
    const int*   iedg = (const int*)d_in[1];
    const int*   user_id = (const int*)d_in[2];
    const int*   item_id = (const int*)d_in[3];
    const float* uval = (const float*)d_in[4];
    const float* ival = (const float*)d_in[5];
    const float* umat = (const float*)d_in[6];
    const float* imat = (const float*)d_in[7];
    const float* W_u1 = (const float*)d_in[8];
    const float* as_u1 = (const float*)d_in[9];
    const float* ad_u1 = (const float*)d_in[10];
    const float* W_u2 = (const float*)d_in[11];
    const float* as_u2 = (const float*)d_in[12];
    const float* ad_u2 = (const float*)d_in[13];
    const float* W_i1 = (const float*)d_in[14];
    const float* as_i1 = (const float*)d_in[15];
    const float* ad_i1 = (const float*)d_in[16];
    const float* W_i2 = (const float*)d_in[17];
    const float* as_i2 = (const float*)d_in[18];
    const float* ad_i2 = (const float*)d_in[19];

    float *h_u, *h_i, *out1_u, *out1_i, *uout2, *iout2;
    float *ssrc_u, *sdst_u, *ssrc_i, *sdst_i, *cev_u, *cev_i;
    uint32_t *wph, *wpl;
    int *off_u, *off_i, *csrc_u, *csrc_i;
    cudaGetSymbolAddress((void**)&h_u, g_h_u);
    cudaGetSymbolAddress((void**)&h_i, g_h_i);
    cudaGetSymbolAddress((void**)&out1_u, g_out1_u);
    cudaGetSymbolAddress((void**)&out1_i, g_out1_i);
    cudaGetSymbolAddress((void**)&uout2, g_uout2);
    cudaGetSymbolAddress((void**)&iout2, g_iout2);
    cudaGetSymbolAddress((void**)&ssrc_u, g_ssrc_u);
    cudaGetSymbolAddress((void**)&sdst_u, g_sdst_u);
    cudaGetSymbolAddress((void**)&ssrc_i, g_ssrc_i);
    cudaGetSymbolAddress((void**)&sdst_i, g_sdst_i);
    cudaGetSymbolAddress((void**)&wph, g_wp_hi);
    cudaGetSymbolAddress((void**)&wpl, g_wp_lo);
    cudaGetSymbolAddress((void**)&off_u, g_off_u);
    cudaGetSymbolAddress((void**)&off_i, g_off_i);
    cudaGetSymbolAddress((void**)&csrc_u, g_csrc_u);
    cudaGetSymbolAddress((void**)&csrc_i, g_csrc_i);
    cudaGetSymbolAddress((void**)&cev_u, g_cev_u);
    cudaGetSymbolAddress((void**)&cev_i, g_cev_i);

    cudaFuncSetAttribute(gemm_mma_kernel<0>, cudaFuncAttributeMaxDynamicSharedMemorySize, SMEM_TOT);
    cudaFuncSetAttribute(gemm_mma_kernel<1>, cudaFuncAttributeMaxDynamicSharedMemorySize, SMEM_TOT);

    const int TB = 256;
    const int WSTRIDE = DIM * 64;

    // weight prep (layer order: 0=i1, 1=i2, 2=u1, 3=u2)
    prep_w_kernel<<<4 * DIM * 64 / TB, TB>>>(W_i1, W_i2, W_u1, W_u2);

    // merged CSR build for both graphs
    zero_cnt_kernel<<<(NU + TB) / TB, TB>>>();
    count_kernel<<<(EU + TB - 1) / TB, TB>>>(uedg + EU, iedg + EI);
    scan_a_kernel<<<NBI_SC + NBU_SC, 1024>>>();
    scan_b_kernel<<<1, 32>>>();
    scan_c_kernel<<<(NU + TB - 1) / TB, TB>>>();
    scatter_kernel<<<(EU + TB - 1) / TB, TB>>>(uedg, uval, iedg, ival);

    // ---- layer 1 (both graphs merged) ----
    GemmArgs gi1 = { imat, wph + 0 * WSTRIDE, wpl + 0 * WSTRIDE, as_i1, ad_i1,
                     h_i, ssrc_i, sdst_i, NI };
    GemmArgs gu1 = { umat, wph + 2 * WSTRIDE, wpl + 2 * WSTRIDE, as_u1, ad_u1,
                     h_u, ssrc_u, sdst_u, NU };
    gemm_mma_kernel<0><<<NBI_G + NBU_G, 256, SMEM_TOT>>>(gi1, gu1);

    AggArgs ai1 = { off_i, csrc_i, cev_i, ssrc_i, sdst_i, h_i, out1_i, NI };
    AggArgs au1 = { off_u, csrc_u, cev_u, ssrc_u, sdst_u, h_u, out1_u, NU };
    agg_csr_kernel<<<AB_I + AB_U, 256>>>(ai1, au1);

    // ---- layer 2 (both graphs merged) ----
    GemmArgs gi2 = { out1_i, wph + 1 * WSTRIDE, wpl + 1 * WSTRIDE, as_i2, ad_i2,
                     h_i, ssrc_i, sdst_i, NI };
    GemmArgs gu2 = { out1_u, wph + 3 * WSTRIDE, wpl + 3 * WSTRIDE, as_u2, ad_u2,
                     h_u, ssrc_u, sdst_u, NU };
    gemm_mma_kernel<1><<<NBI_G + NBU_G, 256, SMEM_TOT>>>(gi2, gu2);

    AggArgs ai2 = { off_i, csrc_i, cev_i, ssrc_i, sdst_i, h_i, iout2, NI };
    AggArgs au2 = { off_u, csrc_u, cev_u, ssrc_u, sdst_u, h_u, uout2, NU };
    agg_csr_kernel<<<AB_I + AB_U, 256>>>(ai2, au2);

    gather_kernel<<<(2 * BATCH * DIM) / TB, TB>>>(uout2, iout2, user_id, item_id, (float*)d_out);
}